// round 16
// baseline (speedup 1.0000x reference)
#include <cuda_runtime.h>
#include <math.h>

#define C_    6
#define A_    1024
#define HW_   16384
#define NROWS 65536
#define NPIX  65536

#define SEG_GRID   592
#define CON_TILES  512
#define MEGA_GRID  (SEG_GRID + CON_TILES)   // 1104

// ---------------- device scratch (self-cleaning across graph replays) --------
__device__ float g_sums[C_ * A_];
__device__ int   g_cnti[4][6];     // replicated per reader-slot; atomicExch-cleared
__device__ float g_L1;
__device__ float g_L2c[C_];
__device__ float g_Se[C_];

// ---------------- f32x2 packed helpers (sm_100+) ----------------
__device__ __forceinline__ unsigned long long pk(float lo, float hi) {
    unsigned long long r;
    asm("mov.b64 %0, {%1, %2};" : "=l"(r) : "f"(lo), "f"(hi));
    return r;
}
__device__ __forceinline__ void upk(unsigned long long v, float& lo, float& hi) {
    asm("mov.b64 {%0, %1}, %2;" : "=f"(lo), "=f"(hi) : "l"(v));
}
__device__ __forceinline__ unsigned long long fma2(unsigned long long a,
                                                   unsigned long long b,
                                                   unsigned long long c) {
    unsigned long long d;
    asm("fma.rn.f32x2 %0, %1, %2, %3;" : "=l"(d) : "l"(a), "l"(b), "l"(c));
    return d;
}

// ================= mega kernel: seg + contrast ===============================
// Launched with PDL: all heavy streaming work runs BEFORE the grid-dependency
// sync; only the final atomic write-backs (which touch cross-replay scratch)
// wait for the previous replay's meanfin to finish consuming/zeroing it.

__device__ __forceinline__ void seg_accum(int c, const float4& v, float4 acc[6],
                                          unsigned long long& cnt64) {
    if ((unsigned)c >= 6u) return;
    cnt64 += 1ull << (c << 3);      // packed per-class count (max 111 rows < 255)
    switch (c) {
#define SEG_CASE(i) \
        case i: acc[i].x += v.x; acc[i].y += v.y; acc[i].z += v.z; acc[i].w += v.w; break;
        SEG_CASE(0) SEG_CASE(1) SEG_CASE(2) SEG_CASE(3) SEG_CASE(4) SEG_CASE(5)
#undef SEG_CASE
    }
}

__device__ __forceinline__ void seg_body(int segIdx,
                                         const float* __restrict__ src,
                                         const int* __restrict__ labels) {
    const int col = threadIdx.x << 2;
    float4 acc[6];
#pragma unroll
    for (int c = 0; c < 6; c++) acc[c] = make_float4(0.f, 0.f, 0.f, 0.f);
    unsigned long long cnt64 = 0ull;

    const int stride = SEG_GRID;
    int r = segIdx;
    for (; r + 3 * stride < NROWS; r += 4 * stride) {
        int l0 = labels[r];
        int l1 = labels[r + stride];
        int l2 = labels[r + 2 * stride];
        int l3 = labels[r + 3 * stride];
        float4 v0 = __ldcs((const float4*)(src + (size_t)r * A_ + col));
        float4 v1 = __ldcs((const float4*)(src + (size_t)(r + stride) * A_ + col));
        float4 v2 = __ldcs((const float4*)(src + (size_t)(r + 2 * stride) * A_ + col));
        float4 v3 = __ldcs((const float4*)(src + (size_t)(r + 3 * stride) * A_ + col));
        seg_accum(l0, v0, acc, cnt64);
        seg_accum(l1, v1, acc, cnt64);
        seg_accum(l2, v2, acc, cnt64);
        seg_accum(l3, v3, acc, cnt64);
    }
    for (; r < NROWS; r += stride) {
        int l0 = labels[r];
        float4 v0 = __ldcs((const float4*)(src + (size_t)r * A_ + col));
        seg_accum(l0, v0, acc, cnt64);
    }

    // wait for previous replay's meanfin before touching cross-replay scratch
    cudaGridDependencySynchronize();

#pragma unroll
    for (int c = 0; c < 6; c++) {
        atomicAdd(&g_sums[c * A_ + col + 0], acc[c].x);
        atomicAdd(&g_sums[c * A_ + col + 1], acc[c].y);
        atomicAdd(&g_sums[c * A_ + col + 2], acc[c].z);
        atomicAdd(&g_sums[c * A_ + col + 3], acc[c].w);
    }
    if (threadIdx.x == 0) {
#pragma unroll
        for (int c = 0; c < 6; c++) {
            int v = (int)((cnt64 >> (c << 3)) & 0xFFull);
            if (v) {
#pragma unroll
                for (int s = 0; s < 4; s++) atomicAdd(&g_cnti[s][c], v);
            }
        }
    }
}

__device__ __forceinline__ void contrast_body(int T,
                                              const float* __restrict__ Proto,
                                              const float* __restrict__ tarfeat,
                                              const float* __restrict__ tarout,
                                              float* sProto, float (*sEx)[256],
                                              float (*sR)[4], float* sInvN,
                                              float (*sTo)[128]) {
    const int tid = threadIdx.x;
    const int lane = tid & 31;
    const int wid = tid >> 5;

    const int b = T >> 7;
    const int pixBase = (T & 127) << 7;

    // load RAW proto; per-class inverse norms in-CTA (warps 0..5)
    for (int i = tid; i < C_ * A_ / 4; i += 256)
        reinterpret_cast<float4*>(sProto)[i] = reinterpret_cast<const float4*>(Proto)[i];

    // prefetch the epilogue's tarout values now; DRAM latency hides under main loop
    if (tid < 128) {
        const float* to = tarout + (size_t)b * ((size_t)C_ * HW_) + pixBase + tid;
#pragma unroll
        for (int c = 0; c < 6; c++) sTo[c][tid] = __ldcs(to + (size_t)c * HW_);
    }
    __syncthreads();
    if (wid < 6) {
        const float* pc = sProto + wid * A_;
        float ss = 0.f;
#pragma unroll 8
        for (int i = lane; i < A_; i += 32) ss = fmaf(pc[i], pc[i], ss);
#pragma unroll
        for (int o = 16; o > 0; o >>= 1) ss += __shfl_xor_sync(0xffffffffu, ss, o);
        if (lane == 0) sInvN[wid] = rsqrtf(fmaxf(ss, 1e-24f));
    }
    __syncthreads();

    const int pixLoc = tid & 127;
    const int chBase = (tid >> 7) << 9;

    const float* p = tarfeat + (size_t)b * ((size_t)A_ * HW_)
                   + (size_t)chBase * HW_ + pixBase + pixLoc;
    const float* pf = sProto + chBase;

    unsigned long long d2[6], ss2 = 0ull;
#pragma unroll
    for (int c = 0; c < 6; c++) d2[c] = 0ull;

#pragma unroll 1
    for (int a = 0; a < 512; a += 16) {
        float v[16];
#pragma unroll
        for (int j = 0; j < 16; j++) v[j] = __ldcs(p + (size_t)j * HW_);
        p += (size_t)16 * HW_;
#pragma unroll
        for (int jq = 0; jq < 4; jq++) {
            unsigned long long vv0 = pk(v[4 * jq + 0], v[4 * jq + 1]);
            unsigned long long vv1 = pk(v[4 * jq + 2], v[4 * jq + 3]);
            ss2 = fma2(vv0, vv0, ss2);
            ss2 = fma2(vv1, vv1, ss2);
#pragma unroll
            for (int c = 0; c < 6; c++) {
                float4 pp = *reinterpret_cast<const float4*>(pf + c * A_ + a + 4 * jq);
                d2[c] = fma2(vv0, pk(pp.x, pp.y), d2[c]);
                d2[c] = fma2(vv1, pk(pp.z, pp.w), d2[c]);
            }
        }
    }

#pragma unroll
    for (int c = 0; c < 6; c++) {
        float lo, hi;
        upk(d2[c], lo, hi);
        sEx[c][tid] = lo + hi;
    }
    {
        float lo, hi;
        upk(ss2, lo, hi);
        sEx[6][tid] = lo + hi;
    }
    __syncthreads();

    // epilogue (tarout already staged in smem)
    float L1p = 0.f, P2[6], E[6];
#pragma unroll
    for (int c = 0; c < 6; c++) { P2[c] = 0.f; E[c] = 0.f; }

    if (tid < 128) {
        float d[6], ss;
#pragma unroll
        for (int c = 0; c < 6; c++) d[c] = sEx[c][tid] + sEx[c][tid + 128];
        ss = sEx[6][tid] + sEx[6][tid + 128];

        const float inv = rsqrtf(fmaxf(ss, 1e-24f));

        float s1 = 0.f;
#pragma unroll
        for (int c = 0; c < 6; c++) {
            E[c] = __expf(sTo[c][tid]);
            s1 += E[c];
        }
#pragma unroll
        for (int c = 0; c < 6; c++) {
            float con = d[c] * inv * sInvN[c];
            P2[c] = E[c] * con;
            L1p += P2[c];
        }
        L1p /= s1;
    }

#pragma unroll
    for (int o = 16; o > 0; o >>= 1) {
        L1p += __shfl_xor_sync(0xffffffffu, L1p, o);
#pragma unroll
        for (int c = 0; c < 6; c++) {
            P2[c] += __shfl_xor_sync(0xffffffffu, P2[c], o);
            E[c]  += __shfl_xor_sync(0xffffffffu, E[c], o);
        }
    }
    if (lane == 0 && wid < 4) {
        sR[0][wid] = L1p;
#pragma unroll
        for (int c = 0; c < 6; c++) {
            sR[1 + c][wid] = P2[c];
            sR[7 + c][wid] = E[c];
        }
    }
    __syncthreads();

    // wait for previous replay's meanfin before touching cross-replay scratch
    cudaGridDependencySynchronize();

    if (tid == 0)
        atomicAdd(&g_L1, sR[0][0] + sR[0][1] + sR[0][2] + sR[0][3]);
    if (tid >= 32 && tid < 38) {
        int c = tid - 32;
        atomicAdd(&g_L2c[c], sR[1 + c][0] + sR[1 + c][1] + sR[1 + c][2] + sR[1 + c][3]);
        atomicAdd(&g_Se[c],  sR[7 + c][0] + sR[7 + c][1] + sR[7 + c][2] + sR[7 + c][3]);
    }
}

// R12 mapping (best known): even bids < 1024 -> contrast tile bid/2;
// odd bids < 1024 -> seg slice bid/2; bids >= 1024 -> seg slice bid-512.
__global__ void __launch_bounds__(256, 4) mega_kernel(const float* __restrict__ Proto,
                                                      const float* __restrict__ srcfeat,
                                                      const int* __restrict__ labels,
                                                      const float* __restrict__ tarfeat,
                                                      const float* __restrict__ tarout) {
    __shared__ float sProto[C_ * A_];
    __shared__ float sEx[7][256];
    __shared__ float sR[13][4];
    __shared__ float sInvN[6];
    __shared__ float sTo[6][128];

    const int bid = blockIdx.x;
    if (bid < 1024) {
        if ((bid & 1) == 0) contrast_body(bid >> 1, Proto, tarfeat, tarout,
                                          sProto, sEx, sR, sInvN, sTo);
        else                seg_body(bid >> 1, srcfeat, labels);
    } else {
        seg_body(bid - 512, srcfeat, labels);
    }
}

// ---------------- kernel 2: finalize mean + loss, then self-clean ------------
__global__ void __launch_bounds__(256) meanfin_kernel(float* __restrict__ out, int out_size) {
    cudaGridDependencySynchronize();

    __shared__ float sCnt;
    const int tid = threadIdx.x;
    const int cls = blockIdx.x >> 2;
    const int slot = blockIdx.x & 3;

    if (tid == 0) {
        int v = atomicExch(&g_cnti[slot][cls], 0);
        sCnt = fmaxf((float)v, 1.0f);
    }
    __syncthreads();

    const int i = blockIdx.x * 256 + tid;
    if (i < C_ * A_ && (i + 1) < out_size) {
        out[1 + i] = g_sums[i] / sCnt;
        g_sums[i] = 0.f;                       // self-clean for next call
    }
    if (i == 0 && out_size >= 1) {
        float loss1 = 1.0f - g_L1 * (1.0f / (float)NPIX);
        float s2 = 0.f;
#pragma unroll
        for (int c = 0; c < 6; c++) s2 += g_L2c[c] / g_Se[c];
        float loss2 = 1.0f - s2 * (1.0f / (float)C_);
        out[0] = loss1 + loss2;
        g_L1 = 0.f;
#pragma unroll
        for (int c = 0; c < 6; c++) { g_L2c[c] = 0.f; g_Se[c] = 0.f; }
    }
}

// ---------------- launch: 2 kernels, BOTH via PDL ----------------
extern "C" void kernel_launch(void* const* d_in, const int* in_sizes, int n_in,
                              void* d_out, int out_size) {
    const float* Proto   = (const float*)d_in[0];
    const float* srcfeat = (const float*)d_in[1];
    const float* tarfeat = (const float*)d_in[2];
    const float* tarout  = (const float*)d_in[3];
    const int* labels    = (const int*)d_in[4];
    float* out = (float*)d_out;

    cudaLaunchAttribute attrs[1];
    attrs[0].id = cudaLaunchAttributeProgrammaticStreamSerialization;
    attrs[0].val.programmaticStreamSerializationAllowed = 1;

    cudaLaunchConfig_t cfgM = {};
    cfgM.gridDim = dim3(MEGA_GRID, 1, 1);
    cfgM.blockDim = dim3(256, 1, 1);
    cfgM.dynamicSmemBytes = 0;
    cfgM.stream = 0;
    cfgM.attrs = attrs;
    cfgM.numAttrs = 1;
    cudaLaunchKernelEx(&cfgM, mega_kernel, Proto, srcfeat, labels, tarfeat, tarout);

    cudaLaunchConfig_t cfgF = {};
    cfgF.gridDim = dim3(24, 1, 1);
    cfgF.blockDim = dim3(256, 1, 1);
    cfgF.dynamicSmemBytes = 0;
    cfgF.stream = 0;
    cfgF.attrs = attrs;
    cfgF.numAttrs = 1;
    cudaLaunchKernelEx(&cfgF, meanfin_kernel, out, out_size);
}

// round 17
// speedup vs baseline: 1.2062x; 1.2062x over previous
#include <cuda_runtime.h>
#include <math.h>

#define C_    6
#define A_    1024
#define HW_   16384
#define NROWS 65536
#define NPIX  65536

#define SEG_GRID   592
#define CON_TILES  512
#define MEGA_GRID  (SEG_GRID + CON_TILES)   // 1104

// ---------------- device scratch (self-cleaning across graph replays) --------
__device__ float g_sums[C_ * A_];
__device__ int   g_cnti[4][6];     // replicated per reader-slot; atomicExch-cleared
__device__ float g_L1;
__device__ float g_L2c[C_];
__device__ float g_Se[C_];

// ---------------- f32x2 packed helpers (sm_100+) ----------------
__device__ __forceinline__ unsigned long long pk(float lo, float hi) {
    unsigned long long r;
    asm("mov.b64 %0, {%1, %2};" : "=l"(r) : "f"(lo), "f"(hi));
    return r;
}
__device__ __forceinline__ void upk(unsigned long long v, float& lo, float& hi) {
    asm("mov.b64 {%0, %1}, %2;" : "=f"(lo), "=f"(hi) : "l"(v));
}
__device__ __forceinline__ unsigned long long fma2(unsigned long long a,
                                                   unsigned long long b,
                                                   unsigned long long c) {
    unsigned long long d;
    asm("fma.rn.f32x2 %0, %1, %2, %3;" : "=l"(d) : "l"(a), "l"(b), "l"(c));
    return d;
}

// ================= mega kernel: seg + contrast ===============================

__device__ __forceinline__ void seg_accum(int c, const float4& v, float4 acc[6],
                                          unsigned long long& cnt64) {
    if ((unsigned)c >= 6u) return;
    cnt64 += 1ull << (c << 3);      // packed per-class count (max 111 rows < 255)
    switch (c) {
#define SEG_CASE(i) \
        case i: acc[i].x += v.x; acc[i].y += v.y; acc[i].z += v.z; acc[i].w += v.w; break;
        SEG_CASE(0) SEG_CASE(1) SEG_CASE(2) SEG_CASE(3) SEG_CASE(4) SEG_CASE(5)
#undef SEG_CASE
    }
}

__device__ __forceinline__ void seg_body(int segIdx,
                                         const float* __restrict__ src,
                                         const int* __restrict__ labels) {
    const int col = threadIdx.x << 2;
    float4 acc[6];
#pragma unroll
    for (int c = 0; c < 6; c++) acc[c] = make_float4(0.f, 0.f, 0.f, 0.f);
    unsigned long long cnt64 = 0ull;

    const int stride = SEG_GRID;
    int r = segIdx;
    for (; r + 3 * stride < NROWS; r += 4 * stride) {
        int l0 = labels[r];
        int l1 = labels[r + stride];
        int l2 = labels[r + 2 * stride];
        int l3 = labels[r + 3 * stride];
        float4 v0 = __ldcs((const float4*)(src + (size_t)r * A_ + col));
        float4 v1 = __ldcs((const float4*)(src + (size_t)(r + stride) * A_ + col));
        float4 v2 = __ldcs((const float4*)(src + (size_t)(r + 2 * stride) * A_ + col));
        float4 v3 = __ldcs((const float4*)(src + (size_t)(r + 3 * stride) * A_ + col));
        seg_accum(l0, v0, acc, cnt64);
        seg_accum(l1, v1, acc, cnt64);
        seg_accum(l2, v2, acc, cnt64);
        seg_accum(l3, v3, acc, cnt64);
    }
    for (; r < NROWS; r += stride) {
        int l0 = labels[r];
        float4 v0 = __ldcs((const float4*)(src + (size_t)r * A_ + col));
        seg_accum(l0, v0, acc, cnt64);
    }

#pragma unroll
    for (int c = 0; c < 6; c++) {
        atomicAdd(&g_sums[c * A_ + col + 0], acc[c].x);
        atomicAdd(&g_sums[c * A_ + col + 1], acc[c].y);
        atomicAdd(&g_sums[c * A_ + col + 2], acc[c].z);
        atomicAdd(&g_sums[c * A_ + col + 3], acc[c].w);
    }
    if (threadIdx.x == 0) {
#pragma unroll
        for (int c = 0; c < 6; c++) {
            int v = (int)((cnt64 >> (c << 3)) & 0xFFull);
            if (v) {
#pragma unroll
                for (int s = 0; s < 4; s++) atomicAdd(&g_cnti[s][c], v);
            }
        }
    }
}

__device__ __forceinline__ void contrast_body(int T,
                                              const float* __restrict__ Proto,
                                              const float* __restrict__ tarfeat,
                                              const float* __restrict__ tarout,
                                              float* sProto, float (*sEx)[256],
                                              float (*sR)[4], float* sInvN,
                                              float (*sTo)[128]) {
    const int tid = threadIdx.x;
    const int lane = tid & 31;
    const int wid = tid >> 5;

    const int b = T >> 7;
    const int pixBase = (T & 127) << 7;

    // load RAW proto; per-class inverse norms in-CTA (warps 0..5)
    for (int i = tid; i < C_ * A_ / 4; i += 256)
        reinterpret_cast<float4*>(sProto)[i] = reinterpret_cast<const float4*>(Proto)[i];

    // prefetch the epilogue's tarout values now; DRAM latency hides under main loop
    if (tid < 128) {
        const float* to = tarout + (size_t)b * ((size_t)C_ * HW_) + pixBase + tid;
#pragma unroll
        for (int c = 0; c < 6; c++) sTo[c][tid] = __ldcs(to + (size_t)c * HW_);
    }
    __syncthreads();
    if (wid < 6) {
        const float* pc = sProto + wid * A_;
        float ss = 0.f;
#pragma unroll 8
        for (int i = lane; i < A_; i += 32) ss = fmaf(pc[i], pc[i], ss);
#pragma unroll
        for (int o = 16; o > 0; o >>= 1) ss += __shfl_xor_sync(0xffffffffu, ss, o);
        if (lane == 0) sInvN[wid] = rsqrtf(fmaxf(ss, 1e-24f));
    }
    __syncthreads();

    const int pixLoc = tid & 127;
    const int chBase = (tid >> 7) << 9;

    const float* p = tarfeat + (size_t)b * ((size_t)A_ * HW_)
                   + (size_t)chBase * HW_ + pixBase + pixLoc;
    const float* pf = sProto + chBase;

    unsigned long long d2[6], ss2 = 0ull;
#pragma unroll
    for (int c = 0; c < 6; c++) d2[c] = 0ull;

#pragma unroll 1
    for (int a = 0; a < 512; a += 16) {
        float v[16];
#pragma unroll
        for (int j = 0; j < 16; j++) v[j] = __ldcs(p + (size_t)j * HW_);
        p += (size_t)16 * HW_;
#pragma unroll
        for (int jq = 0; jq < 4; jq++) {
            unsigned long long vv0 = pk(v[4 * jq + 0], v[4 * jq + 1]);
            unsigned long long vv1 = pk(v[4 * jq + 2], v[4 * jq + 3]);
            ss2 = fma2(vv0, vv0, ss2);
            ss2 = fma2(vv1, vv1, ss2);
#pragma unroll
            for (int c = 0; c < 6; c++) {
                float4 pp = *reinterpret_cast<const float4*>(pf + c * A_ + a + 4 * jq);
                d2[c] = fma2(vv0, pk(pp.x, pp.y), d2[c]);
                d2[c] = fma2(vv1, pk(pp.z, pp.w), d2[c]);
            }
        }
    }

#pragma unroll
    for (int c = 0; c < 6; c++) {
        float lo, hi;
        upk(d2[c], lo, hi);
        sEx[c][tid] = lo + hi;
    }
    {
        float lo, hi;
        upk(ss2, lo, hi);
        sEx[6][tid] = lo + hi;
    }
    __syncthreads();

    // epilogue (tarout already staged in smem)
    float L1p = 0.f, P2[6], E[6];
#pragma unroll
    for (int c = 0; c < 6; c++) { P2[c] = 0.f; E[c] = 0.f; }

    if (tid < 128) {
        float d[6], ss;
#pragma unroll
        for (int c = 0; c < 6; c++) d[c] = sEx[c][tid] + sEx[c][tid + 128];
        ss = sEx[6][tid] + sEx[6][tid + 128];

        const float inv = rsqrtf(fmaxf(ss, 1e-24f));

        float s1 = 0.f;
#pragma unroll
        for (int c = 0; c < 6; c++) {
            E[c] = __expf(sTo[c][tid]);
            s1 += E[c];
        }
#pragma unroll
        for (int c = 0; c < 6; c++) {
            float con = d[c] * inv * sInvN[c];
            P2[c] = E[c] * con;
            L1p += P2[c];
        }
        L1p /= s1;
    }

#pragma unroll
    for (int o = 16; o > 0; o >>= 1) {
        L1p += __shfl_xor_sync(0xffffffffu, L1p, o);
#pragma unroll
        for (int c = 0; c < 6; c++) {
            P2[c] += __shfl_xor_sync(0xffffffffu, P2[c], o);
            E[c]  += __shfl_xor_sync(0xffffffffu, E[c], o);
        }
    }
    if (lane == 0 && wid < 4) {
        sR[0][wid] = L1p;
#pragma unroll
        for (int c = 0; c < 6; c++) {
            sR[1 + c][wid] = P2[c];
            sR[7 + c][wid] = E[c];
        }
    }
    __syncthreads();
    if (tid == 0)
        atomicAdd(&g_L1, sR[0][0] + sR[0][1] + sR[0][2] + sR[0][3]);
    if (tid >= 32 && tid < 38) {
        int c = tid - 32;
        atomicAdd(&g_L2c[c], sR[1 + c][0] + sR[1 + c][1] + sR[1 + c][2] + sR[1 + c][3]);
        atomicAdd(&g_Se[c],  sR[7 + c][0] + sR[7 + c][1] + sR[7 + c][2] + sR[7 + c][3]);
    }
}

// R12 mapping (best known): even bids < 1024 -> contrast tile bid/2;
// odd bids < 1024 -> seg slice bid/2; bids >= 1024 -> seg slice bid-512.
__global__ void __launch_bounds__(256, 4) mega_kernel(const float* __restrict__ Proto,
                                                      const float* __restrict__ srcfeat,
                                                      const int* __restrict__ labels,
                                                      const float* __restrict__ tarfeat,
                                                      const float* __restrict__ tarout) {
    __shared__ float sProto[C_ * A_];
    __shared__ float sEx[7][256];
    __shared__ float sR[13][4];
    __shared__ float sInvN[6];
    __shared__ float sTo[6][128];

    const int bid = blockIdx.x;
    if (bid < 1024) {
        if ((bid & 1) == 0) contrast_body(bid >> 1, Proto, tarfeat, tarout,
                                          sProto, sEx, sR, sInvN, sTo);
        else                seg_body(bid >> 1, srcfeat, labels);
    } else {
        seg_body(bid - 512, srcfeat, labels);
    }
}

// ---------------- kernel 2: finalize mean + loss, then self-clean ------------
// PDL-dependent (trailing small kernel ONLY): CTAs may be placed while mega
// drains; first instruction blocks on the grid dependency. All consumed state
// lives in L2 (atomics), no SM ever holds an L1 copy, so plain loads are safe.
__global__ void __launch_bounds__(256) meanfin_kernel(float* __restrict__ out, int out_size) {
    cudaGridDependencySynchronize();

    __shared__ float sCnt;
    const int tid = threadIdx.x;
    const int cls = blockIdx.x >> 2;
    const int slot = blockIdx.x & 3;

    if (tid == 0) {
        int v = atomicExch(&g_cnti[slot][cls], 0);
        sCnt = fmaxf((float)v, 1.0f);
    }
    __syncthreads();

    const int i = blockIdx.x * 256 + tid;
    if (i < C_ * A_ && (i + 1) < out_size) {
        out[1 + i] = g_sums[i] / sCnt;
        g_sums[i] = 0.f;                       // self-clean for next call
    }
    if (i == 0 && out_size >= 1) {
        float loss1 = 1.0f - g_L1 * (1.0f / (float)NPIX);
        float s2 = 0.f;
#pragma unroll
        for (int c = 0; c < 6; c++) s2 += g_L2c[c] / g_Se[c];
        float loss2 = 1.0f - s2 * (1.0f / (float)C_);
        out[0] = loss1 + loss2;
        g_L1 = 0.f;
#pragma unroll
        for (int c = 0; c < 6; c++) { g_L2c[c] = 0.f; g_Se[c] = 0.f; }
    }
}

// ---------------- launch: 2 kernels, PDL on the trailing one only ----------
extern "C" void kernel_launch(void* const* d_in, const int* in_sizes, int n_in,
                              void* d_out, int out_size) {
    const float* Proto   = (const float*)d_in[0];
    const float* srcfeat = (const float*)d_in[1];
    const float* tarfeat = (const float*)d_in[2];
    const float* tarout  = (const float*)d_in[3];
    const int* labels    = (const int*)d_in[4];
    float* out = (float*)d_out;

    mega_kernel<<<MEGA_GRID, 256>>>(Proto, srcfeat, labels, tarfeat, tarout);

    cudaLaunchConfig_t cfg = {};
    cfg.gridDim = dim3(24, 1, 1);
    cfg.blockDim = dim3(256, 1, 1);
    cfg.dynamicSmemBytes = 0;
    cfg.stream = 0;
    cudaLaunchAttribute attrs[1];
    attrs[0].id = cudaLaunchAttributeProgrammaticStreamSerialization;
    attrs[0].val.programmaticStreamSerializationAllowed = 1;
    cfg.attrs = attrs;
    cfg.numAttrs = 1;
    cudaLaunchKernelEx(&cfg, meanfin_kernel, out, out_size);
}